// round 8
// baseline (speedup 1.0000x reference)
#include <cuda_runtime.h>
#include <cuda_bf16.h>
#include <math.h>

#define NN 200000
#define EE 6400000
#define GG 2000
#define ROW 16      // floats per state row (64B)
#define SBS 512
#define NB1 ((NN + SBS - 1) / SBS)

__device__ __align__(256) float  g_S0[NN * ROW];
__device__ __align__(256) float  g_S1[NN * ROW];
__device__ __align__(16)  float4 g_c4[NN];
__device__ __align__(256) float  g_gs[GG * ROW];
__device__ __align__(32)  float4 g_rec[(size_t)EE * 2];  // 32B/edge, to-sorted: {geo4 | from,pad,pad,pad}
__device__ int g_cnt[NN];    // degree (incoming)
__device__ int g_start[NN];  // CSR start (exclusive scan)
__device__ int g_off[NN];    // bump cursor for scatter
__device__ int g_part[SBS];

__device__ __forceinline__ float tanh_acc(float x) {
    float ax = fabsf(x);
    float e;
    asm("ex2.approx.f32 %0, %1;" : "=f"(e) : "f"(ax * -2.8853900817779268f));
    float r;
    asm("rcp.approx.f32 %0, %1;" : "=f"(r) : "f"(1.0f + e));
    return copysignf((1.0f - e) * r, x);
}
__device__ __forceinline__ float softplus_acc(float x) {
    return log1pf(expf(-fabsf(x))) + fmaxf(x, 0.0f);
}
__device__ __forceinline__ void ld_v8(const float* p, float* s) {
    asm("ld.global.nc.v8.f32 {%0,%1,%2,%3,%4,%5,%6,%7}, [%8];"
        : "=f"(s[0]), "=f"(s[1]), "=f"(s[2]), "=f"(s[3]),
          "=f"(s[4]), "=f"(s[5]), "=f"(s[6]), "=f"(s[7])
        : "l"(p));
}
__device__ __forceinline__ void st_v8(float* p, const float* s) {
    asm volatile("st.global.v8.f32 [%0], {%1,%2,%3,%4,%5,%6,%7,%8};"
                 :: "l"(p), "f"(s[0]), "f"(s[1]), "f"(s[2]), "f"(s[3]),
                    "f"(s[4]), "f"(s[5]), "f"(s[6]), "f"(s[7]) : "memory");
}
__device__ __forceinline__ void red_v4(float* p, float a, float b, float c, float d) {
    asm volatile("red.global.add.v4.f32 [%0], {%1,%2,%3,%4};"
                 :: "l"(p), "f"(a), "f"(b), "f"(c), "f"(d) : "memory");
}
__device__ __forceinline__ void red_v2(float* p, float a, float b) {
    asm volatile("red.global.add.v2.f32 [%0], {%1,%2};"
                 :: "l"(p), "f"(a), "f"(b) : "memory");
}

__global__ void init_kernel(const float* __restrict__ coords) {
    int i = blockIdx.x * blockDim.x + threadIdx.x;
    if (i < NN)       g_c4[i] = make_float4(coords[3*i], coords[3*i+1], coords[3*i+2], 0.f);
    if (i < NN)       g_cnt[i] = 0;
    if (i < GG * ROW) g_gs[i] = 0.f;
}

__global__ void hist_kernel(const int* __restrict__ nt) {
    int e = blockIdx.x * blockDim.x + threadIdx.x;
    if (e < EE) atomicAdd(&g_cnt[nt[e]], 1);
}

__global__ void scan1_kernel() {
    __shared__ int s[SBS];
    int tid = threadIdx.x;
    int gid = blockIdx.x * SBS + tid;
    int v = (gid < NN) ? g_cnt[gid] : 0;
    s[tid] = v;
    __syncthreads();
#pragma unroll
    for (int d = 1; d < SBS; d <<= 1) {
        int t = (tid >= d) ? s[tid - d] : 0;
        __syncthreads();
        s[tid] += t;
        __syncthreads();
    }
    if (gid < NN) g_start[gid] = s[tid] - v;        // exclusive (pre block offset)
    if (tid == SBS - 1) g_part[blockIdx.x] = s[SBS - 1];
}

__global__ void scan2_kernel() {
    __shared__ int s[SBS];
    int tid = threadIdx.x;
    int v = (tid < NB1) ? g_part[tid] : 0;
    s[tid] = v;
    __syncthreads();
#pragma unroll
    for (int d = 1; d < SBS; d <<= 1) {
        int t = (tid >= d) ? s[tid - d] : 0;
        __syncthreads();
        s[tid] += t;
        __syncthreads();
    }
    if (tid < NB1) g_part[tid] = s[tid] - v;
}

__global__ void scan3_kernel() {
    int gid = blockIdx.x * SBS + threadIdx.x;
    if (gid < NN) {
        int st = g_start[gid] + g_part[blockIdx.x];
        g_start[gid] = st;
        g_off[gid] = st;
    }
}

// Compute geo per edge, place 32B record {geo, from} at to-sorted slot.
__global__ void scatter_kernel(const int* __restrict__ nf, const int* __restrict__ nt,
                               const float* __restrict__ el, const float* __restrict__ ev) {
    int e = blockIdx.x * blockDim.x + threadIdx.x;
    if (e >= EE) return;
    int from = nf[e];
    int to   = nt[e];
    float4 cf = g_c4[from];
    float4 ct = g_c4[to];
    float e0 = ev[3*e], e1 = ev[3*e+1], e2 = ev[3*e+2];

    float r[8];
    r[0] = el[e];
    r[1] = fabsf(cf.x) + fabsf(cf.y) + fabsf(cf.z);
    r[2] = cf.x*ct.x + cf.y*ct.y + cf.z*ct.z;
    r[3] = cf.x*e0 + cf.y*e1 + cf.z*e2;
    r[4] = __int_as_float(from);
    r[5] = 0.f; r[6] = 0.f; r[7] = 0.f;

    int pos = atomicAdd(&g_off[to], 1);
    st_v8((float*)(g_rec + 2*(size_t)pos), r);
}

// Pull-mode round: warp per node, zero atomics on state.
// MODE 0: first round (state==0), write Sout = sum.
// MODE 1: middle round, write Sout = Sin + sum.
// MODE 2: last round, no state write; reduce (Sin + sum) into graph accumulator.
template <int MODE>
__global__ void pull_kernel(const float* __restrict__ Wm, const float* __restrict__ bm,
                            const float* __restrict__ Sin, float* __restrict__ Sout,
                            const int* __restrict__ ngi) {
    __shared__ float sW[140];
    __shared__ float sB[10];
    int tid = threadIdx.x;
    if (tid < 140) sW[tid] = Wm[tid];
    if (tid < 10)  sB[tid] = bm[tid];
    __syncthreads();

    int lane = tid & 31;
    int n = blockIdx.x * 8 + (tid >> 5);   // grid = 25000 blocks * 8 warps = NN exactly

    int start = g_start[n];
    int deg   = g_cnt[n];

    float acc[10];
#pragma unroll
    for (int j = 0; j < 10; j++) acc[j] = 0.f;

    for (int k = lane; k < deg; k += 32) {
        float r[8];
        ld_v8((const float*)(g_rec + 2*(size_t)(start + k)), r);

        float m[10];
#pragma unroll
        for (int j = 0; j < 10; j++)
            m[j] = sB[j] + r[0]*sW[100+j] + r[1]*sW[110+j] + r[2]*sW[120+j] + r[3]*sW[130+j];

        if (MODE != 0) {
            int from = __float_as_int(r[4]);
            const float* srow = Sin + (size_t)from * ROW;
            float s[10];
            ld_v8(srow, s);
            asm("ld.global.nc.v2.f32 {%0,%1}, [%2];" : "=f"(s[8]), "=f"(s[9]) : "l"(srow + 8));
#pragma unroll
            for (int i = 0; i < 10; i++) {
#pragma unroll
                for (int j = 0; j < 10; j++) m[j] += s[i] * sW[i*10+j];
            }
        }
#pragma unroll
        for (int j = 0; j < 10; j++) acc[j] += tanh_acc(m[j]);
    }

    // warp reduction
#pragma unroll
    for (int j = 0; j < 10; j++) {
#pragma unroll
        for (int d = 16; d > 0; d >>= 1)
            acc[j] += __shfl_xor_sync(0xFFFFFFFFu, acc[j], d);
    }

    if (lane == 0) {
        if (MODE != 0) {
            const float* srow = Sin + (size_t)n * ROW;
            float s[10];
            ld_v8(srow, s);
            asm("ld.global.nc.v2.f32 {%0,%1}, [%2];" : "=f"(s[8]), "=f"(s[9]) : "l"(srow + 8));
#pragma unroll
            for (int j = 0; j < 10; j++) acc[j] += s[j];
        }
        if (MODE == 2) {
            int g = ngi[n];
            float* dst = g_gs + (size_t)g * ROW;
            red_v4(dst,     acc[0], acc[1], acc[2], acc[3]);
            red_v4(dst + 4, acc[4], acc[5], acc[6], acc[7]);
            red_v2(dst + 8, acc[8], acc[9]);
        } else {
            float* drow = Sout + (size_t)n * ROW;
            float w[8] = {acc[0], acc[1], acc[2], acc[3], acc[4], acc[5], acc[6], acc[7]};
            st_v8(drow, w);
            asm volatile("st.global.v2.f32 [%0], {%1,%2};"
                         :: "l"(drow + 8), "f"(acc[8]), "f"(acc[9]) : "memory");
        }
    }
}

__global__ void out_kernel(const float* __restrict__ Wo, const float* __restrict__ bo,
                           float* __restrict__ out) {
    int g = blockIdx.x * blockDim.x + threadIdx.x;
    if (g >= GG) return;
    float ev[4];
#pragma unroll
    for (int k = 0; k < 4; k++) ev[k] = bo[k];
#pragma unroll
    for (int j = 0; j < 10; j++) {
        float s = g_gs[g * ROW + j];
#pragma unroll
        for (int k = 0; k < 4; k++) ev[k] += s * Wo[j*4+k];
    }
    out[4*g+0] = ev[0];
    out[4*g+1] = softplus_acc(ev[1]);
    out[4*g+2] = softplus_acc(ev[2]) + 1.0f;
    out[4*g+3] = softplus_acc(ev[3]);
}

extern "C" void kernel_launch(void* const* d_in, const int* in_sizes, int n_in,
                              void* d_out, int out_size) {
    const float* coords = (const float*)d_in[0];
    const float* el     = (const float*)d_in[1];
    const float* evv    = (const float*)d_in[2];
    const float* Wm     = (const float*)d_in[3];
    const float* bm     = (const float*)d_in[4];
    const float* Wo     = (const float*)d_in[5];
    const float* bo     = (const float*)d_in[6];
    const int*   nf     = (const int*)d_in[7];
    const int*   nt     = (const int*)d_in[8];
    const int*   ngi    = (const int*)d_in[9];
    float* out = (float*)d_out;

    float *S0, *S1;
    cudaGetSymbolAddress((void**)&S0, g_S0);
    cudaGetSymbolAddress((void**)&S1, g_S1);

    const int TB = 256;
    int grid_init = (GG * ROW > NN ? GG * ROW : NN);
    grid_init = (grid_init + TB - 1) / TB;
    int grid_edge = (EE + TB - 1) / TB;
    int grid_pull = NN / 8;   // 25000 blocks, 8 warps each = NN warps
    int grid_out  = (GG + TB - 1) / TB;

    // build: hist -> scan -> to-sorted records (geo computed here)
    init_kernel<<<grid_init, TB>>>(coords);
    hist_kernel<<<grid_edge, TB>>>(nt);
    scan1_kernel<<<NB1, SBS>>>();
    scan2_kernel<<<1, SBS>>>();
    scan3_kernel<<<NB1, SBS>>>();
    scatter_kernel<<<grid_edge, TB>>>(nf, nt, el, evv);

    // rounds (pull-mode, no atomics on state)
    pull_kernel<0><<<grid_pull, TB>>>(Wm, bm, S0, S1, ngi);   // S1 = sum
    pull_kernel<1><<<grid_pull, TB>>>(Wm, bm, S1, S0, ngi);   // S0 = S1 + sum
    pull_kernel<2><<<grid_pull, TB>>>(Wm, bm, S0, S1, ngi);   // g_gs += S0 + sum
    out_kernel<<<grid_out, TB>>>(Wo, bo, out);
}

// round 9
// speedup vs baseline: 2.6678x; 2.6678x over previous
#include <cuda_runtime.h>
#include <cuda_bf16.h>
#include <math.h>

#define NN 200000
#define EE 6400000
#define GG 2000
#define ROW 16      // floats per state row (64B)
#define SBS 512
#define NB1 ((NN + SBS - 1) / SBS)

__device__ __align__(256) float  g_S0[NN * ROW];
__device__ __align__(256) float  g_S1[NN * ROW];
__device__ __align__(16)  float4 g_c4[NN];
__device__ __align__(256) float  g_gs[GG * ROW];
// 32B record per edge, sorted by `to`: {el, g1, g3, cf.x, cf.y, cf.z, from, to}
__device__ __align__(32)  float4 g_rec[(size_t)EE * 2];
__device__ int g_cnt[NN];
__device__ int g_off[NN];
__device__ int g_part[SBS];

__device__ __forceinline__ float tanh_acc(float x) {
    float ax = fabsf(x);
    float e;
    asm("ex2.approx.f32 %0, %1;" : "=f"(e) : "f"(ax * -2.8853900817779268f));
    float r;
    asm("rcp.approx.f32 %0, %1;" : "=f"(r) : "f"(1.0f + e));
    return copysignf((1.0f - e) * r, x);
}
__device__ __forceinline__ float softplus_acc(float x) {
    return log1pf(expf(-fabsf(x))) + fmaxf(x, 0.0f);
}
__device__ __forceinline__ void ld_v8(const float* p, float* s) {
    asm("ld.global.nc.v8.f32 {%0,%1,%2,%3,%4,%5,%6,%7}, [%8];"
        : "=f"(s[0]), "=f"(s[1]), "=f"(s[2]), "=f"(s[3]),
          "=f"(s[4]), "=f"(s[5]), "=f"(s[6]), "=f"(s[7])
        : "l"(p));
}
__device__ __forceinline__ void st_v8(float* p, const float* s) {
    asm volatile("st.global.v8.f32 [%0], {%1,%2,%3,%4,%5,%6,%7,%8};"
                 :: "l"(p), "f"(s[0]), "f"(s[1]), "f"(s[2]), "f"(s[3]),
                    "f"(s[4]), "f"(s[5]), "f"(s[6]), "f"(s[7]) : "memory");
}
__device__ __forceinline__ void red_v4(float* p, float a, float b, float c, float d) {
    asm volatile("red.global.add.v4.f32 [%0], {%1,%2,%3,%4};"
                 :: "l"(p), "f"(a), "f"(b), "f"(c), "f"(d) : "memory");
}
__device__ __forceinline__ void red_v2(float* p, float a, float b) {
    asm volatile("red.global.add.v2.f32 [%0], {%1,%2};"
                 :: "l"(p), "f"(a), "f"(b) : "memory");
}
__device__ __forceinline__ void red_row(float* dst, const float* a) {
    red_v4(dst,     a[0], a[1], a[2], a[3]);
    red_v4(dst + 4, a[4], a[5], a[6], a[7]);
    red_v2(dst + 8, a[8], a[9]);
}

__global__ void init_kernel(const float* __restrict__ coords) {
    int i = blockIdx.x * blockDim.x + threadIdx.x;
    if (i < NN * ROW) g_S1[i] = 0.f;
    if (i < NN)       g_c4[i] = make_float4(coords[3*i], coords[3*i+1], coords[3*i+2], 0.f);
    if (i < NN)       g_cnt[i] = 0;
    if (i < GG * ROW) g_gs[i] = 0.f;
}

__global__ void hist_kernel(const int* __restrict__ nt) {
    int e = blockIdx.x * blockDim.x + threadIdx.x;
    if (e < EE) atomicAdd(&g_cnt[nt[e]], 1);
}

__global__ void scan1_kernel() {
    __shared__ int s[SBS];
    int tid = threadIdx.x;
    int gid = blockIdx.x * SBS + tid;
    int v = (gid < NN) ? g_cnt[gid] : 0;
    s[tid] = v;
    __syncthreads();
#pragma unroll
    for (int d = 1; d < SBS; d <<= 1) {
        int t = (tid >= d) ? s[tid - d] : 0;
        __syncthreads();
        s[tid] += t;
        __syncthreads();
    }
    if (gid < NN) g_off[gid] = s[tid] - v;
    if (tid == SBS - 1) g_part[blockIdx.x] = s[SBS - 1];
}

__global__ void scan2_kernel() {
    __shared__ int s[SBS];
    int tid = threadIdx.x;
    int v = (tid < NB1) ? g_part[tid] : 0;
    s[tid] = v;
    __syncthreads();
#pragma unroll
    for (int d = 1; d < SBS; d <<= 1) {
        int t = (tid >= d) ? s[tid - d] : 0;
        __syncthreads();
        s[tid] += t;
        __syncthreads();
    }
    if (tid < NB1) g_part[tid] = s[tid] - v;
}

__global__ void scan3_kernel() {
    int gid = blockIdx.x * SBS + threadIdx.x;
    if (gid < NN) g_off[gid] += g_part[blockIdx.x];
}

// Build to-sorted 32B records. NOTE: no ct gather here (g2 computed in rounds).
__global__ void scatter_kernel(const int* __restrict__ nf, const int* __restrict__ nt,
                               const float* __restrict__ el, const float* __restrict__ ev) {
    int e = blockIdx.x * blockDim.x + threadIdx.x;
    if (e >= EE) return;
    int from = nf[e];
    int to   = nt[e];
    float4 cf = g_c4[from];
    float e0 = ev[3*e], e1 = ev[3*e+1], e2 = ev[3*e+2];

    float r[8];
    r[0] = el[e];
    r[1] = fabsf(cf.x) + fabsf(cf.y) + fabsf(cf.z);       // g1
    r[2] = cf.x*e0 + cf.y*e1 + cf.z*e2;                   // g3 (dot2)
    r[3] = cf.x; r[4] = cf.y; r[5] = cf.z;
    r[6] = __int_as_float(from);
    r[7] = __int_as_float(to);

    int pos = atomicAdd(&g_off[to], 1);
    st_v8((float*)(g_rec + 2*(size_t)pos), r);
}

// Thread-per-sorted-edge round with warp segmented reduction on `to`.
// FIRST=true: state==0 (skip gather).
template <bool FIRST>
__global__ void __launch_bounds__(256) round_kernel(
        const float* __restrict__ Wm, const float* __restrict__ bm,
        const float* __restrict__ Sin, float* __restrict__ Sout) {
    __shared__ float sW[140];
    __shared__ float sB[10];
    int tid = threadIdx.x;
    if (tid < 140) sW[tid] = Wm[tid];
    if (tid < 10)  sB[tid] = bm[tid];
    __syncthreads();

    int e = blockIdx.x * blockDim.x + tid;   // EE divisible by 256: no bounds check
    int lane = tid & 31;

    float r[8];
    ld_v8((const float*)(g_rec + 2*(size_t)e), r);
    int to = __float_as_int(r[7]);

    // g2 = dot(cf, c_to): `to` is sorted => near-broadcast load
    float4 ct = g_c4[to];
    float g2 = r[3]*ct.x + r[4]*ct.y + r[5]*ct.z;

    float m[10];
#pragma unroll
    for (int j = 0; j < 10; j++)
        m[j] = sB[j] + r[0]*sW[100+j] + r[1]*sW[110+j] + g2*sW[120+j] + r[2]*sW[130+j];

    if (!FIRST) {
        int from = __float_as_int(r[6]);
        const float* srow = Sin + (size_t)from * ROW;
        float s[10];
        ld_v8(srow, s);
        asm("ld.global.nc.v2.f32 {%0,%1}, [%2];" : "=f"(s[8]), "=f"(s[9]) : "l"(srow + 8));
#pragma unroll
        for (int i = 0; i < 10; i++) {
#pragma unroll
            for (int j = 0; j < 10; j++) m[j] += s[i] * sW[i*10+j];
        }
    }
#pragma unroll
    for (int j = 0; j < 10; j++) m[j] = tanh_acc(m[j]);

    // Segmented suffix-scan over equal-`to` runs (sorted within warp).
    const unsigned FULL = 0xFFFFFFFFu;
#pragma unroll
    for (int d = 1; d < 32; d <<= 1) {
        int t2 = __shfl_down_sync(FULL, to, d);
        bool ok = (lane + d < 32) && (t2 == to);
#pragma unroll
        for (int j = 0; j < 10; j++) {
            float v = __shfl_down_sync(FULL, m[j], d);
            if (ok) m[j] += v;
        }
    }
    int tprev = __shfl_up_sync(FULL, to, 1);
    bool head = (lane == 0) || (tprev != to);
    if (head) red_row(Sout + (size_t)to * ROW, m);
}

__global__ void copy_kernel(const float4* __restrict__ src, float4* __restrict__ dst) {
    int i = blockIdx.x * blockDim.x + threadIdx.x;
    if (i < NN * 4) dst[i] = src[i];
}

__global__ void node_kernel(const int* __restrict__ ngi, const float* __restrict__ S) {
    int i = blockIdx.x * blockDim.x + threadIdx.x;
    if (i >= NN) return;
    int g = ngi[i];
    const float* srow = S + (size_t)i * ROW;
    float s[10];
    ld_v8(srow, s);
    asm("ld.global.nc.v2.f32 {%0,%1}, [%2];" : "=f"(s[8]), "=f"(s[9]) : "l"(srow + 8));
    red_row(g_gs + (size_t)g * ROW, s);
}

__global__ void out_kernel(const float* __restrict__ Wo, const float* __restrict__ bo,
                           float* __restrict__ out) {
    int g = blockIdx.x * blockDim.x + threadIdx.x;
    if (g >= GG) return;
    float ev[4];
#pragma unroll
    for (int k = 0; k < 4; k++) ev[k] = bo[k];
#pragma unroll
    for (int j = 0; j < 10; j++) {
        float s = g_gs[g * ROW + j];
#pragma unroll
        for (int k = 0; k < 4; k++) ev[k] += s * Wo[j*4+k];
    }
    out[4*g+0] = ev[0];
    out[4*g+1] = softplus_acc(ev[1]);
    out[4*g+2] = softplus_acc(ev[2]) + 1.0f;
    out[4*g+3] = softplus_acc(ev[3]);
}

extern "C" void kernel_launch(void* const* d_in, const int* in_sizes, int n_in,
                              void* d_out, int out_size) {
    const float* coords = (const float*)d_in[0];
    const float* el     = (const float*)d_in[1];
    const float* evv    = (const float*)d_in[2];
    const float* Wm     = (const float*)d_in[3];
    const float* bm     = (const float*)d_in[4];
    const float* Wo     = (const float*)d_in[5];
    const float* bo     = (const float*)d_in[6];
    const int*   nf     = (const int*)d_in[7];
    const int*   nt     = (const int*)d_in[8];
    const int*   ngi    = (const int*)d_in[9];
    float* out = (float*)d_out;

    float *S0, *S1;
    cudaGetSymbolAddress((void**)&S0, g_S0);
    cudaGetSymbolAddress((void**)&S1, g_S1);

    const int TB = 256;
    int grid_init = (NN * ROW + TB - 1) / TB;
    int grid_copy = (NN * 4 + TB - 1) / TB;
    int grid_edge = (EE + TB - 1) / TB;   // 25000
    int grid_node = (NN + TB - 1) / TB;
    int grid_out  = (GG + TB - 1) / TB;

    // build: hist -> scan -> to-sorted records
    init_kernel<<<grid_init, TB>>>(coords);
    hist_kernel<<<grid_edge, TB>>>(nt);
    scan1_kernel<<<NB1, SBS>>>();
    scan2_kernel<<<1, SBS>>>();
    scan3_kernel<<<NB1, SBS>>>();
    scatter_kernel<<<grid_edge, TB>>>(nf, nt, el, evv);

    // round 0: state = 0, accumulate into S1 (zeroed in init)
    round_kernel<true><<<grid_edge, TB>>>(Wm, bm, S0, S1);
    // round 1: read S1, accumulate into S0 := S1
    copy_kernel<<<grid_copy, TB>>>((const float4*)S1, (float4*)S0);
    round_kernel<false><<<grid_edge, TB>>>(Wm, bm, S1, S0);
    // round 2: read S0, accumulate into S1 := S0
    copy_kernel<<<grid_copy, TB>>>((const float4*)S0, (float4*)S1);
    round_kernel<false><<<grid_edge, TB>>>(Wm, bm, S0, S1);
    // graph reduce + output head
    node_kernel<<<grid_node, TB>>>(ngi, S1);
    out_kernel<<<grid_out, TB>>>(Wo, bo, out);
}

// round 12
// speedup vs baseline: 2.9105x; 1.0910x over previous
#include <cuda_runtime.h>
#include <cuda_bf16.h>
#include <cuda_fp16.h>
#include <math.h>

#define NN 200000
#define EE 6400000
#define GG 2000
#define ROW 16      // floats per fp32 state row (64B)
#define MROW 16     // halves per fp16 mirror row (32B)
#define SBS 512
#define NB1 ((NN + SBS - 1) / SBS)

__device__ __align__(256) float  g_S[NN * ROW];    // fp32 state accumulator
__device__ __align__(256) __half g_M[NN * MROW];   // fp16 mirror for gathers
__device__ __align__(16)  float4 g_c4[NN];
__device__ __align__(256) float  g_gs[GG * ROW];
// 32B record per edge, sorted by `to`: {el, g1, g3, cf.x, cf.y, cf.z, from, to}
__device__ __align__(32)  float4 g_rec[(size_t)EE * 2];
__device__ int g_off[NN];
__device__ int g_part[SBS];
__device__ int g_cnt[NN];

__device__ __forceinline__ float tanh_acc(float x) {
    float ax = fabsf(x);
    float e;
    asm("ex2.approx.f32 %0, %1;" : "=f"(e) : "f"(ax * -2.8853900817779268f));
    float r;
    asm("rcp.approx.f32 %0, %1;" : "=f"(r) : "f"(1.0f + e));
    return copysignf((1.0f - e) * r, x);
}
__device__ __forceinline__ float softplus_acc(float x) {
    return log1pf(expf(-fabsf(x))) + fmaxf(x, 0.0f);
}
__device__ __forceinline__ void ld_v8(const float* p, float* s) {
    asm("ld.global.nc.v8.f32 {%0,%1,%2,%3,%4,%5,%6,%7}, [%8];"
        : "=f"(s[0]), "=f"(s[1]), "=f"(s[2]), "=f"(s[3]),
          "=f"(s[4]), "=f"(s[5]), "=f"(s[6]), "=f"(s[7])
        : "l"(p));
}
__device__ __forceinline__ void st_v8(float* p, const float* s) {
    asm volatile("st.global.v8.f32 [%0], {%1,%2,%3,%4,%5,%6,%7,%8};"
                 :: "l"(p), "f"(s[0]), "f"(s[1]), "f"(s[2]), "f"(s[3]),
                    "f"(s[4]), "f"(s[5]), "f"(s[6]), "f"(s[7]) : "memory");
}
__device__ __forceinline__ void red_v4(float* p, float a, float b, float c, float d) {
    asm volatile("red.global.add.v4.f32 [%0], {%1,%2,%3,%4};"
                 :: "l"(p), "f"(a), "f"(b), "f"(c), "f"(d) : "memory");
}
__device__ __forceinline__ void red_v2(float* p, float a, float b) {
    asm volatile("red.global.add.v2.f32 [%0], {%1,%2};"
                 :: "l"(p), "f"(a), "f"(b) : "memory");
}
__device__ __forceinline__ void red_row(float* dst, const float* a) {
    red_v4(dst,     a[0], a[1], a[2], a[3]);
    red_v4(dst + 4, a[4], a[5], a[6], a[7]);
    red_v2(dst + 8, a[8], a[9]);
}

__global__ void init_kernel(const float* __restrict__ coords) {
    int i = blockIdx.x * blockDim.x + threadIdx.x;
    if (i < NN * ROW) g_S[i] = 0.f;
    if (i < NN)       g_c4[i] = make_float4(coords[3*i], coords[3*i+1], coords[3*i+2], 0.f);
    if (i < NN)       g_cnt[i] = 0;
    if (i < GG * ROW) g_gs[i] = 0.f;
}

__global__ void hist_kernel(const int* __restrict__ nt) {
    int e = blockIdx.x * blockDim.x + threadIdx.x;
    if (e < EE) atomicAdd(&g_cnt[nt[e]], 1);
}

__global__ void scan1_kernel() {
    __shared__ int s[SBS];
    int tid = threadIdx.x;
    int gid = blockIdx.x * SBS + tid;
    int v = (gid < NN) ? g_cnt[gid] : 0;
    s[tid] = v;
    __syncthreads();
#pragma unroll
    for (int d = 1; d < SBS; d <<= 1) {
        int t = (tid >= d) ? s[tid - d] : 0;
        __syncthreads();
        s[tid] += t;
        __syncthreads();
    }
    if (gid < NN) g_off[gid] = s[tid] - v;
    if (tid == SBS - 1) g_part[blockIdx.x] = s[SBS - 1];
}

__global__ void scan2_kernel() {
    __shared__ int s[SBS];
    int tid = threadIdx.x;
    int v = (tid < NB1) ? g_part[tid] : 0;
    s[tid] = v;
    __syncthreads();
#pragma unroll
    for (int d = 1; d < SBS; d <<= 1) {
        int t = (tid >= d) ? s[tid - d] : 0;
        __syncthreads();
        s[tid] += t;
        __syncthreads();
    }
    if (tid < NB1) g_part[tid] = s[tid] - v;
}

__global__ void scan3_kernel() {
    int gid = blockIdx.x * SBS + threadIdx.x;
    if (gid < NN) g_off[gid] += g_part[blockIdx.x];
}

__global__ void scatter_kernel(const int* __restrict__ nf, const int* __restrict__ nt,
                               const float* __restrict__ el, const float* __restrict__ ev) {
    int e = blockIdx.x * blockDim.x + threadIdx.x;
    if (e >= EE) return;
    int from = nf[e];
    int to   = nt[e];
    float4 cf = g_c4[from];
    float e0 = ev[3*e], e1 = ev[3*e+1], e2 = ev[3*e+2];

    float r[8];
    r[0] = el[e];
    r[1] = fabsf(cf.x) + fabsf(cf.y) + fabsf(cf.z);       // g1
    r[2] = cf.x*e0 + cf.y*e1 + cf.z*e2;                   // g3
    r[3] = cf.x; r[4] = cf.y; r[5] = cf.z;
    r[6] = __int_as_float(from);
    r[7] = __int_as_float(to);

    int pos = atomicAdd(&g_off[to], 1);
    st_v8((float*)(g_rec + 2*(size_t)pos), r);
}

// fp32 state row -> fp16 mirror row (32B)
__global__ void cvt_kernel() {
    int n = blockIdx.x * blockDim.x + threadIdx.x;
    if (n >= NN) return;
    const float* srow = g_S + (size_t)n * ROW;
    float w[8];
    unsigned u[8];
#pragma unroll
    for (int k = 0; k < 5; k++) {
        __half2 h = __floats2half2_rn(srow[2*k], srow[2*k+1]);
        u[k] = *reinterpret_cast<unsigned*>(&h);
    }
    u[5] = u[6] = u[7] = 0u;
#pragma unroll
    for (int k = 0; k < 8; k++) w[k] = __uint_as_float(u[k]);
    st_v8((float*)(g_M + (size_t)n * MROW), w);
}

// Thread-per-sorted-edge round, warp segmented suffix-scan, heads red into fp32 S.
template <bool FIRST>
__global__ void __launch_bounds__(256) round_kernel(
        const float* __restrict__ Wm, const float* __restrict__ bm) {
    __shared__ float sW[140];
    __shared__ float sB[10];
    int tid = threadIdx.x;
    if (tid < 140) sW[tid] = Wm[tid];
    if (tid < 10)  sB[tid] = bm[tid];
    __syncthreads();

    int e = blockIdx.x * blockDim.x + tid;   // EE % 256 == 0
    int lane = tid & 31;

    float r[8];
    ld_v8((const float*)(g_rec + 2*(size_t)e), r);
    int to = __float_as_int(r[7]);

    float4 ct = g_c4[to];                    // sorted `to` => near-broadcast
    float g2 = r[3]*ct.x + r[4]*ct.y + r[5]*ct.z;

    float m[10];
#pragma unroll
    for (int j = 0; j < 10; j++)
        m[j] = sB[j] + r[0]*sW[100+j] + r[1]*sW[110+j] + g2*sW[120+j] + r[2]*sW[130+j];

    if (!FIRST) {
        int from = __float_as_int(r[6]);
        float raw[8];
        ld_v8((const float*)(g_M + (size_t)from * MROW), raw);   // ONE random op
        float s[10];
#pragma unroll
        for (int k = 0; k < 5; k++) {
            unsigned u = __float_as_uint(raw[k]);
            __half2 h = *reinterpret_cast<__half2*>(&u);
            float2 f = __half22float2(h);
            s[2*k] = f.x; s[2*k+1] = f.y;
        }
#pragma unroll
        for (int i = 0; i < 10; i++) {
#pragma unroll
            for (int j = 0; j < 10; j++) m[j] += s[i] * sW[i*10+j];
        }
    }
#pragma unroll
    for (int j = 0; j < 10; j++) m[j] = tanh_acc(m[j]);

    // Segmented suffix-scan: precompute segment end, then 5 predicated steps.
    const unsigned FULL = 0xFFFFFFFFu;
    int tprev = __shfl_up_sync(FULL, to, 1);
    bool head = (lane == 0) || (tprev != to);
    unsigned hm = __ballot_sync(FULL, head);
    unsigned mask_after = hm & ~((2u << lane) - 1u);
    int seg_end = mask_after ? (__ffs(mask_after) - 2) : 31;
#pragma unroll
    for (int d = 1; d < 32; d <<= 1) {
        bool ok = (lane + d) <= seg_end;
#pragma unroll
        for (int j = 0; j < 10; j++) {
            float v = __shfl_down_sync(FULL, m[j], d);
            if (ok) m[j] += v;
        }
    }
    if (head) red_row(g_S + (size_t)to * ROW, m);
}

__global__ void node_kernel(const int* __restrict__ ngi) {
    int i = blockIdx.x * blockDim.x + threadIdx.x;
    if (i >= NN) return;
    int g = ngi[i];
    const float* srow = g_S + (size_t)i * ROW;
    float s[10];
    ld_v8(srow, s);
    asm("ld.global.nc.v2.f32 {%0,%1}, [%2];" : "=f"(s[8]), "=f"(s[9]) : "l"(srow + 8));
    red_row(g_gs + (size_t)g * ROW, s);
}

__global__ void out_kernel(const float* __restrict__ Wo, const float* __restrict__ bo,
                           float* __restrict__ out) {
    int g = blockIdx.x * blockDim.x + threadIdx.x;
    if (g >= GG) return;
    float ev[4];
#pragma unroll
    for (int k = 0; k < 4; k++) ev[k] = bo[k];
#pragma unroll
    for (int j = 0; j < 10; j++) {
        float s = g_gs[g * ROW + j];
#pragma unroll
        for (int k = 0; k < 4; k++) ev[k] += s * Wo[j*4+k];
    }
    out[4*g+0] = ev[0];
    out[4*g+1] = softplus_acc(ev[1]);
    out[4*g+2] = softplus_acc(ev[2]) + 1.0f;
    out[4*g+3] = softplus_acc(ev[3]);
}

extern "C" void kernel_launch(void* const* d_in, const int* in_sizes, int n_in,
                              void* d_out, int out_size) {
    const float* coords = (const float*)d_in[0];
    const float* el     = (const float*)d_in[1];
    const float* evv    = (const float*)d_in[2];
    const float* Wm     = (const float*)d_in[3];
    const float* bm     = (const float*)d_in[4];
    const float* Wo     = (const float*)d_in[5];
    const float* bo     = (const float*)d_in[6];
    const int*   nf     = (const int*)d_in[7];
    const int*   nt     = (const int*)d_in[8];
    const int*   ngi    = (const int*)d_in[9];
    float* out = (float*)d_out;

    const int TB = 256;
    int grid_init = (NN * ROW + TB - 1) / TB;
    int grid_edge = (EE + TB - 1) / TB;   // 25000
    int grid_node = (NN + TB - 1) / TB;
    int grid_out  = (GG + TB - 1) / TB;

    // build: hist -> scan -> to-sorted records
    init_kernel<<<grid_init, TB>>>(coords);
    hist_kernel<<<grid_edge, TB>>>(nt);
    scan1_kernel<<<NB1, SBS>>>();
    scan2_kernel<<<1, SBS>>>();
    scan3_kernel<<<NB1, SBS>>>();
    scatter_kernel<<<grid_edge, TB>>>(nf, nt, el, evv);

    // round 1: state0 = 0 -> S = state1
    round_kernel<true><<<grid_edge, TB>>>(Wm, bm);
    cvt_kernel<<<grid_node, TB>>>();                    // M = fp16(state1)
    // round 2: gather M, S += msg -> S = state2
    round_kernel<false><<<grid_edge, TB>>>(Wm, bm);
    cvt_kernel<<<grid_node, TB>>>();                    // M = fp16(state2)
    // round 3: gather M, S += msg -> S = state3
    round_kernel<false><<<grid_edge, TB>>>(Wm, bm);
    // graph reduce + output head
    node_kernel<<<grid_node, TB>>>(ngi);
    out_kernel<<<grid_out, TB>>>(Wo, bo, out);
}

// round 15
// speedup vs baseline: 3.3792x; 1.1610x over previous
#include <cuda_runtime.h>
#include <cuda_bf16.h>
#include <cuda_fp16.h>
#include <math.h>

#define NN 200000
#define EE 6400000
#define GG 2000
#define ROW 16      // floats per fp32 state row (64B)
#define MROW 16     // halves per fp16 P-mirror row (32B)
#define SBS 512
#define NB1 ((NN + SBS - 1) / SBS)

__device__ __align__(256) float  g_S[NN * ROW];    // fp32 state accumulator
__device__ __align__(256) __half g_M[NN * MROW];   // fp16 mirror of P[n] = b + s·W + g1·W11
__device__ __align__(16)  float4 g_c4[NN];         // {coord.xyz, g1}
__device__ __align__(256) float  g_gs[GG * ROW];
// 32B record per edge, sorted by `to`: {el, g1, g3, cf.x, cf.y, cf.z, from, to}
__device__ __align__(32)  float4 g_rec[(size_t)EE * 2];
__device__ int g_off[NN];
__device__ int g_part[SBS];
__device__ int g_cnt[NN];

__device__ __forceinline__ float tanh_acc(float x) {
    float ax = fabsf(x);
    float e;
    asm("ex2.approx.f32 %0, %1;" : "=f"(e) : "f"(ax * -2.8853900817779268f));
    float r;
    asm("rcp.approx.f32 %0, %1;" : "=f"(r) : "f"(1.0f + e));
    return copysignf((1.0f - e) * r, x);
}
__device__ __forceinline__ float softplus_acc(float x) {
    return log1pf(expf(-fabsf(x))) + fmaxf(x, 0.0f);
}
__device__ __forceinline__ void ld_v8(const float* p, float* s) {
    asm("ld.global.nc.v8.f32 {%0,%1,%2,%3,%4,%5,%6,%7}, [%8];"
        : "=f"(s[0]), "=f"(s[1]), "=f"(s[2]), "=f"(s[3]),
          "=f"(s[4]), "=f"(s[5]), "=f"(s[6]), "=f"(s[7])
        : "l"(p));
}
__device__ __forceinline__ void st_v8(float* p, const float* s) {
    asm volatile("st.global.v8.f32 [%0], {%1,%2,%3,%4,%5,%6,%7,%8};"
                 :: "l"(p), "f"(s[0]), "f"(s[1]), "f"(s[2]), "f"(s[3]),
                    "f"(s[4]), "f"(s[5]), "f"(s[6]), "f"(s[7]) : "memory");
}
__device__ __forceinline__ void red_v4(float* p, float a, float b, float c, float d) {
    asm volatile("red.global.add.v4.f32 [%0], {%1,%2,%3,%4};"
                 :: "l"(p), "f"(a), "f"(b), "f"(c), "f"(d) : "memory");
}
__device__ __forceinline__ void red_v2(float* p, float a, float b) {
    asm volatile("red.global.add.v2.f32 [%0], {%1,%2};"
                 :: "l"(p), "f"(a), "f"(b) : "memory");
}
__device__ __forceinline__ void red_row(float* dst, const float* a) {
    red_v4(dst,     a[0], a[1], a[2], a[3]);
    red_v4(dst + 4, a[4], a[5], a[6], a[7]);
    red_v2(dst + 8, a[8], a[9]);
}

__global__ void init_kernel(const float* __restrict__ coords) {
    int i = blockIdx.x * blockDim.x + threadIdx.x;
    if (i < NN * ROW) g_S[i] = 0.f;
    if (i < NN) {
        float x = coords[3*i], y = coords[3*i+1], z = coords[3*i+2];
        g_c4[i] = make_float4(x, y, z, fabsf(x) + fabsf(y) + fabsf(z));  // .w = g1
    }
    if (i < NN)       g_cnt[i] = 0;
    if (i < GG * ROW) g_gs[i] = 0.f;
}

__global__ void hist_kernel(const int* __restrict__ nt) {
    int e = blockIdx.x * blockDim.x + threadIdx.x;
    if (e < EE) atomicAdd(&g_cnt[nt[e]], 1);
}

__global__ void scan1_kernel() {
    __shared__ int s[SBS];
    int tid = threadIdx.x;
    int gid = blockIdx.x * SBS + tid;
    int v = (gid < NN) ? g_cnt[gid] : 0;
    s[tid] = v;
    __syncthreads();
#pragma unroll
    for (int d = 1; d < SBS; d <<= 1) {
        int t = (tid >= d) ? s[tid - d] : 0;
        __syncthreads();
        s[tid] += t;
        __syncthreads();
    }
    if (gid < NN) g_off[gid] = s[tid] - v;
    if (tid == SBS - 1) g_part[blockIdx.x] = s[SBS - 1];
}

__global__ void scan2_kernel() {
    __shared__ int s[SBS];
    int tid = threadIdx.x;
    int v = (tid < NB1) ? g_part[tid] : 0;
    s[tid] = v;
    __syncthreads();
#pragma unroll
    for (int d = 1; d < SBS; d <<= 1) {
        int t = (tid >= d) ? s[tid - d] : 0;
        __syncthreads();
        s[tid] += t;
        __syncthreads();
    }
    if (tid < NB1) g_part[tid] = s[tid] - v;
}

__global__ void scan3_kernel() {
    int gid = blockIdx.x * SBS + threadIdx.x;
    if (gid < NN) g_off[gid] += g_part[blockIdx.x];
}

__global__ void scatter_kernel(const int* __restrict__ nf, const int* __restrict__ nt,
                               const float* __restrict__ el, const float* __restrict__ ev) {
    int e = blockIdx.x * blockDim.x + threadIdx.x;
    if (e >= EE) return;
    int from = nf[e];
    int to   = nt[e];
    float4 cf = g_c4[from];      // .w = g1(from)
    float e0 = ev[3*e], e1 = ev[3*e+1], e2 = ev[3*e+2];

    float r[8];
    r[0] = el[e];
    r[1] = cf.w;                                   // g1
    r[2] = cf.x*e0 + cf.y*e1 + cf.z*e2;            // g3
    r[3] = cf.x; r[4] = cf.y; r[5] = cf.z;
    r[6] = __int_as_float(from);
    r[7] = __int_as_float(to);

    int pos = atomicAdd(&g_off[to], 1);
    st_v8((float*)(g_rec + 2*(size_t)pos), r);
}

// Per-node precompute: P[n] = b + s[n]·W_state + g1(n)*W11  -> fp16 mirror.
// This hoists the 10x10 GEMV out of the 6.4M-edge loop (32x fewer evals).
__global__ void pmat_kernel(const float* __restrict__ Wm, const float* __restrict__ bm) {
    __shared__ float sW[140];
    __shared__ float sB[10];
    int tid = threadIdx.x;
    if (tid < 140) sW[tid] = Wm[tid];
    if (tid < 10)  sB[tid] = bm[tid];
    __syncthreads();

    int n = blockIdx.x * blockDim.x + tid;
    if (n >= NN) return;

    const float* srow = g_S + (size_t)n * ROW;
    float s[10];
    ld_v8(srow, s);
    asm("ld.global.nc.v2.f32 {%0,%1}, [%2];" : "=f"(s[8]), "=f"(s[9]) : "l"(srow + 8));
    float g1 = g_c4[n].w;

    float P[10];
#pragma unroll
    for (int j = 0; j < 10; j++) P[j] = sB[j] + g1 * sW[110 + j];
#pragma unroll
    for (int i = 0; i < 10; i++) {
#pragma unroll
        for (int j = 0; j < 10; j++) P[j] += s[i] * sW[i*10 + j];
    }

    float w[8];
    unsigned u[8];
#pragma unroll
    for (int k = 0; k < 5; k++) {
        __half2 h = __floats2half2_rn(P[2*k], P[2*k+1]);
        u[k] = *reinterpret_cast<unsigned*>(&h);
    }
    u[5] = u[6] = u[7] = 0u;
#pragma unroll
    for (int k = 0; k < 8; k++) w[k] = __uint_as_float(u[k]);
    st_v8((float*)(g_M + (size_t)n * MROW), w);
}

// Thread-per-sorted-edge round. Per-edge math is now only the geo terms.
// FIRST: state==0 -> m = b + el*W10 + g1*W11 + g2*W12 + g3*W13 (no gather).
// else:  m = P[from] + el*W10 + g2*W12 + g3*W13 (g1 folded into P).
template <bool FIRST>
__global__ void __launch_bounds__(256) round_kernel(
        const float* __restrict__ Wm, const float* __restrict__ bm) {
    __shared__ float sG[40];   // rows 10..13 of W (el, g1, g2, g3)
    __shared__ float sB[10];
    int tid = threadIdx.x;
    if (tid < 40) sG[tid] = Wm[100 + tid];
    if (tid < 10) sB[tid] = bm[tid];
    __syncthreads();

    int e = blockIdx.x * blockDim.x + tid;   // EE % 256 == 0
    int lane = tid & 31;

    float r[8];
    ld_v8((const float*)(g_rec + 2*(size_t)e), r);
    int to = __float_as_int(r[7]);

    float4 ct = g_c4[to];                    // sorted `to` => near-broadcast
    float g2 = r[3]*ct.x + r[4]*ct.y + r[5]*ct.z;

    float m[10];
    if (FIRST) {
#pragma unroll
        for (int j = 0; j < 10; j++)
            m[j] = sB[j] + r[0]*sG[j] + r[1]*sG[10+j] + g2*sG[20+j] + r[2]*sG[30+j];
    } else {
        int from = __float_as_int(r[6]);
        float raw[8];
        ld_v8((const float*)(g_M + (size_t)from * MROW), raw);   // ONE random op
#pragma unroll
        for (int k = 0; k < 5; k++) {
            unsigned u = __float_as_uint(raw[k]);
            __half2 h = *reinterpret_cast<__half2*>(&u);
            float2 f = __half22float2(h);
            m[2*k]   = f.x;
            m[2*k+1] = f.y;
        }
#pragma unroll
        for (int j = 0; j < 10; j++)
            m[j] += r[0]*sG[j] + g2*sG[20+j] + r[2]*sG[30+j];
    }
#pragma unroll
    for (int j = 0; j < 10; j++) m[j] = tanh_acc(m[j]);

    // Segmented suffix-scan over equal-`to` runs.
    const unsigned FULL = 0xFFFFFFFFu;
    int tprev = __shfl_up_sync(FULL, to, 1);
    bool head = (lane == 0) || (tprev != to);
    unsigned hm = __ballot_sync(FULL, head);
    unsigned mask_after = hm & ~((2u << lane) - 1u);
    int seg_end = mask_after ? (__ffs(mask_after) - 2) : 31;
#pragma unroll
    for (int d = 1; d < 32; d <<= 1) {
        bool ok = (lane + d) <= seg_end;
#pragma unroll
        for (int j = 0; j < 10; j++) {
            float v = __shfl_down_sync(FULL, m[j], d);
            if (ok) m[j] += v;
        }
    }
    if (head) red_row(g_S + (size_t)to * ROW, m);
}

__global__ void node_kernel(const int* __restrict__ ngi) {
    int i = blockIdx.x * blockDim.x + threadIdx.x;
    if (i >= NN) return;
    int g = ngi[i];
    const float* srow = g_S + (size_t)i * ROW;
    float s[10];
    ld_v8(srow, s);
    asm("ld.global.nc.v2.f32 {%0,%1}, [%2];" : "=f"(s[8]), "=f"(s[9]) : "l"(srow + 8));
    red_row(g_gs + (size_t)g * ROW, s);
}

__global__ void out_kernel(const float* __restrict__ Wo, const float* __restrict__ bo,
                           float* __restrict__ out) {
    int g = blockIdx.x * blockDim.x + threadIdx.x;
    if (g >= GG) return;
    float ev[4];
#pragma unroll
    for (int k = 0; k < 4; k++) ev[k] = bo[k];
#pragma unroll
    for (int j = 0; j < 10; j++) {
        float s = g_gs[g * ROW + j];
#pragma unroll
        for (int k = 0; k < 4; k++) ev[k] += s * Wo[j*4+k];
    }
    out[4*g+0] = ev[0];
    out[4*g+1] = softplus_acc(ev[1]);
    out[4*g+2] = softplus_acc(ev[2]) + 1.0f;
    out[4*g+3] = softplus_acc(ev[3]);
}

extern "C" void kernel_launch(void* const* d_in, const int* in_sizes, int n_in,
                              void* d_out, int out_size) {
    const float* coords = (const float*)d_in[0];
    const float* el     = (const float*)d_in[1];
    const float* evv    = (const float*)d_in[2];
    const float* Wm     = (const float*)d_in[3];
    const float* bm     = (const float*)d_in[4];
    const float* Wo     = (const float*)d_in[5];
    const float* bo     = (const float*)d_in[6];
    const int*   nf     = (const int*)d_in[7];
    const int*   nt     = (const int*)d_in[8];
    const int*   ngi    = (const int*)d_in[9];
    float* out = (float*)d_out;

    const int TB = 256;
    int grid_init = (NN * ROW + TB - 1) / TB;
    int grid_edge = (EE + TB - 1) / TB;   // 25000
    int grid_node = (NN + TB - 1) / TB;
    int grid_out  = (GG + TB - 1) / TB;

    // build: hist -> scan -> to-sorted records
    init_kernel<<<grid_init, TB>>>(coords);
    hist_kernel<<<grid_edge, TB>>>(nt);
    scan1_kernel<<<NB1, SBS>>>();
    scan2_kernel<<<1, SBS>>>();
    scan3_kernel<<<NB1, SBS>>>();
    scatter_kernel<<<grid_edge, TB>>>(nf, nt, el, evv);

    // round 1: state0 = 0 -> S = state1
    round_kernel<true><<<grid_edge, TB>>>(Wm, bm);
    pmat_kernel<<<grid_node, TB>>>(Wm, bm);             // M = fp16(P(state1))
    // round 2
    round_kernel<false><<<grid_edge, TB>>>(Wm, bm);
    pmat_kernel<<<grid_node, TB>>>(Wm, bm);             // M = fp16(P(state2))
    // round 3
    round_kernel<false><<<grid_edge, TB>>>(Wm, bm);
    // graph reduce + output head
    node_kernel<<<grid_node, TB>>>(ngi);
    out_kernel<<<grid_out, TB>>>(Wo, bo, out);
}

// round 16
// speedup vs baseline: 3.7855x; 1.1202x over previous
#include <cuda_runtime.h>
#include <cuda_bf16.h>
#include <cuda_fp16.h>
#include <math.h>

#define NN 200000
#define EE 6400000
#define GG 2000
#define ROW 16      // floats per fp32 state row (64B)
#define MROW 16     // halves per fp16 P-mirror row (32B)
#define SBS 512
#define NB1 ((NN + SBS - 1) / SBS)

__device__ __align__(256) float  g_S[NN * ROW];    // fp32 state accumulator
__device__ __align__(256) __half g_M[NN * MROW];   // fp16 mirror of P[n] = b + s·W + g1·W11
__device__ __align__(16)  float4 g_c4[NN];         // {coord.xyz, g1}
__device__ __align__(256) float  g_gs[GG * ROW];
// 32B record per edge, sorted by `to`: {el, g1, g3, cf.x, cf.y, cf.z, from, to}
__device__ __align__(32)  float4 g_rec[(size_t)EE * 2];
__device__ int g_off[NN];
__device__ int g_part[SBS];
__device__ int g_cnt[NN];

__device__ __forceinline__ float tanh_acc(float x) {
    float ax = fabsf(x);
    float e;
    asm("ex2.approx.f32 %0, %1;" : "=f"(e) : "f"(ax * -2.8853900817779268f));
    float r;
    asm("rcp.approx.f32 %0, %1;" : "=f"(r) : "f"(1.0f + e));
    return copysignf((1.0f - e) * r, x);
}
__device__ __forceinline__ float softplus_acc(float x) {
    return log1pf(expf(-fabsf(x))) + fmaxf(x, 0.0f);
}
__device__ __forceinline__ void ld_v8(const float* p, float* s) {
    asm("ld.global.nc.v8.f32 {%0,%1,%2,%3,%4,%5,%6,%7}, [%8];"
        : "=f"(s[0]), "=f"(s[1]), "=f"(s[2]), "=f"(s[3]),
          "=f"(s[4]), "=f"(s[5]), "=f"(s[6]), "=f"(s[7])
        : "l"(p));
}
__device__ __forceinline__ void st_v8(float* p, const float* s) {
    asm volatile("st.global.v8.f32 [%0], {%1,%2,%3,%4,%5,%6,%7,%8};"
                 :: "l"(p), "f"(s[0]), "f"(s[1]), "f"(s[2]), "f"(s[3]),
                    "f"(s[4]), "f"(s[5]), "f"(s[6]), "f"(s[7]) : "memory");
}
__device__ __forceinline__ void red_v4(float* p, float a, float b, float c, float d) {
    asm volatile("red.global.add.v4.f32 [%0], {%1,%2,%3,%4};"
                 :: "l"(p), "f"(a), "f"(b), "f"(c), "f"(d) : "memory");
}
__device__ __forceinline__ void red_v2(float* p, float a, float b) {
    asm volatile("red.global.add.v2.f32 [%0], {%1,%2};"
                 :: "l"(p), "f"(a), "f"(b) : "memory");
}
__device__ __forceinline__ void red_row(float* dst, const float* a) {
    red_v4(dst,     a[0], a[1], a[2], a[3]);
    red_v4(dst + 4, a[4], a[5], a[6], a[7]);
    red_v2(dst + 8, a[8], a[9]);
}

__global__ void init_kernel(const float* __restrict__ coords) {
    int i = blockIdx.x * blockDim.x + threadIdx.x;
    if (i < NN * ROW) g_S[i] = 0.f;
    if (i < NN) {
        float x = coords[3*i], y = coords[3*i+1], z = coords[3*i+2];
        g_c4[i] = make_float4(x, y, z, fabsf(x) + fabsf(y) + fabsf(z));  // .w = g1
    }
    if (i < NN)       g_cnt[i] = 0;
    if (i < GG * ROW) g_gs[i] = 0.f;
}

// 2 edges per thread
__global__ void hist_kernel(const int* __restrict__ nt) {
    int t = blockIdx.x * blockDim.x + threadIdx.x;
    int e = 2 * t;
    if (e < EE) {
        atomicAdd(&g_cnt[nt[e]], 1);
        atomicAdd(&g_cnt[nt[e + 1]], 1);
    }
}

__global__ void scan1_kernel() {
    __shared__ int s[SBS];
    int tid = threadIdx.x;
    int gid = blockIdx.x * SBS + tid;
    int v = (gid < NN) ? g_cnt[gid] : 0;
    s[tid] = v;
    __syncthreads();
#pragma unroll
    for (int d = 1; d < SBS; d <<= 1) {
        int t = (tid >= d) ? s[tid - d] : 0;
        __syncthreads();
        s[tid] += t;
        __syncthreads();
    }
    if (gid < NN) g_off[gid] = s[tid] - v;
    if (tid == SBS - 1) g_part[blockIdx.x] = s[SBS - 1];
}

__global__ void scan2_kernel() {
    __shared__ int s[SBS];
    int tid = threadIdx.x;
    int v = (tid < NB1) ? g_part[tid] : 0;
    s[tid] = v;
    __syncthreads();
#pragma unroll
    for (int d = 1; d < SBS; d <<= 1) {
        int t = (tid >= d) ? s[tid - d] : 0;
        __syncthreads();
        s[tid] += t;
        __syncthreads();
    }
    if (tid < NB1) g_part[tid] = s[tid] - v;
}

__global__ void scan3_kernel() {
    int gid = blockIdx.x * SBS + threadIdx.x;
    if (gid < NN) g_off[gid] += g_part[blockIdx.x];
}

// 2 edges per thread; MLP-2 on gather/bump/store.
__global__ void scatter_kernel(const int* __restrict__ nf, const int* __restrict__ nt,
                               const float* __restrict__ el, const float* __restrict__ ev) {
    int t = blockIdx.x * blockDim.x + threadIdx.x;
    int e = 2 * t;
    if (e >= EE) return;

#pragma unroll
    for (int q = 0; q < 2; q++) {
        int ee = e + q;
        int from = nf[ee];
        int to   = nt[ee];
        float4 cf = g_c4[from];      // .w = g1(from)
        float e0 = ev[3*ee], e1 = ev[3*ee+1], e2 = ev[3*ee+2];

        float r[8];
        r[0] = el[ee];
        r[1] = cf.w;                                   // g1
        r[2] = cf.x*e0 + cf.y*e1 + cf.z*e2;            // g3
        r[3] = cf.x; r[4] = cf.y; r[5] = cf.z;
        r[6] = __int_as_float(from);
        r[7] = __int_as_float(to);

        int pos = atomicAdd(&g_off[to], 1);
        st_v8((float*)(g_rec + 2*(size_t)pos), r);
    }
}

// Per-node precompute: P[n] = b + s[n]·W_state + g1(n)*W11  -> fp16 mirror.
__global__ void pmat_kernel(const float* __restrict__ Wm, const float* __restrict__ bm) {
    __shared__ float sW[140];
    __shared__ float sB[10];
    int tid = threadIdx.x;
    if (tid < 140) sW[tid] = Wm[tid];
    if (tid < 10)  sB[tid] = bm[tid];
    __syncthreads();

    int n = blockIdx.x * blockDim.x + tid;
    if (n >= NN) return;

    const float* srow = g_S + (size_t)n * ROW;
    float s[10];
    ld_v8(srow, s);
    asm("ld.global.nc.v2.f32 {%0,%1}, [%2];" : "=f"(s[8]), "=f"(s[9]) : "l"(srow + 8));
    float g1 = g_c4[n].w;

    float P[10];
#pragma unroll
    for (int j = 0; j < 10; j++) P[j] = sB[j] + g1 * sW[110 + j];
#pragma unroll
    for (int i = 0; i < 10; i++) {
#pragma unroll
        for (int j = 0; j < 10; j++) P[j] += s[i] * sW[i*10 + j];
    }

    float w[8];
    unsigned u[8];
#pragma unroll
    for (int k = 0; k < 5; k++) {
        __half2 h = __floats2half2_rn(P[2*k], P[2*k+1]);
        u[k] = *reinterpret_cast<unsigned*>(&h);
    }
    u[5] = u[6] = u[7] = 0u;
#pragma unroll
    for (int k = 0; k < 8; k++) w[k] = __uint_as_float(u[k]);
    st_v8((float*)(g_M + (size_t)n * MROW), w);
}

// Compute one edge message from its record (weights in smem sG/sB).
template <bool FIRST>
__device__ __forceinline__ void edge_msg(const float* r, const float* sG, const float* sB,
                                         float* m) {
    // g2 = cf · c_to  (sorted `to` => near-broadcast c4 load)
    int to = __float_as_int(r[7]);
    float4 ct = g_c4[to];
    float g2 = r[3]*ct.x + r[4]*ct.y + r[5]*ct.z;

    if (FIRST) {
#pragma unroll
        for (int j = 0; j < 10; j++)
            m[j] = sB[j] + r[0]*sG[j] + r[1]*sG[10+j] + g2*sG[20+j] + r[2]*sG[30+j];
    } else {
        int from = __float_as_int(r[6]);
        float raw[8];
        ld_v8((const float*)(g_M + (size_t)from * MROW), raw);
#pragma unroll
        for (int k = 0; k < 5; k++) {
            unsigned u = __float_as_uint(raw[k]);
            __half2 h = *reinterpret_cast<__half2*>(&u);
            float2 f = __half22float2(h);
            m[2*k]   = f.x;
            m[2*k+1] = f.y;
        }
#pragma unroll
        for (int j = 0; j < 10; j++)
            m[j] += r[0]*sG[j] + g2*sG[20+j] + r[2]*sG[30+j];
    }
#pragma unroll
    for (int j = 0; j < 10; j++) m[j] = tanh_acc(m[j]);
}

// Paired round: each thread handles sorted edges 2t, 2t+1.
// ~97% of pairs share `to` -> local combine; else rare direct red of the first.
template <bool FIRST>
__global__ void __launch_bounds__(256) round_kernel(
        const float* __restrict__ Wm, const float* __restrict__ bm) {
    __shared__ float sG[40];   // rows 10..13 of W (el, g1, g2, g3)
    __shared__ float sB[10];
    int tid = threadIdx.x;
    if (tid < 40) sG[tid] = Wm[100 + tid];
    if (tid < 10) sB[tid] = bm[tid];
    __syncthreads();

    int t = blockIdx.x * blockDim.x + tid;   // t in [0, EE/2); EE/2 % 256 == 0
    int lane = tid & 31;
    size_t e = 2 * (size_t)t;

    float ra[8], rb[8];
    ld_v8((const float*)(g_rec + 2*e), ra);
    ld_v8((const float*)(g_rec + 2*e + 2), rb);
    int to_a = __float_as_int(ra[7]);
    int to_b = __float_as_int(rb[7]);

    float ma[10], mb[10];
    edge_msg<FIRST>(ra, sG, sB, ma);
    edge_msg<FIRST>(rb, sG, sB, mb);

    float m[10];
    if (to_a == to_b) {
#pragma unroll
        for (int j = 0; j < 10; j++) m[j] = ma[j] + mb[j];
    } else {
        red_row(g_S + (size_t)to_a * ROW, ma);   // rare (~3%)
#pragma unroll
        for (int j = 0; j < 10; j++) m[j] = mb[j];
    }
    int to = to_b;

    // Segmented suffix-scan over equal-`to` runs (to sorted across lanes).
    const unsigned FULL = 0xFFFFFFFFu;
    int tprev = __shfl_up_sync(FULL, to, 1);
    bool head = (lane == 0) || (tprev != to);
    unsigned hm = __ballot_sync(FULL, head);
    unsigned mask_after = hm & ~((2u << lane) - 1u);
    int seg_end = mask_after ? (__ffs(mask_after) - 2) : 31;
#pragma unroll
    for (int d = 1; d < 32; d <<= 1) {
        bool ok = (lane + d) <= seg_end;
#pragma unroll
        for (int j = 0; j < 10; j++) {
            float v = __shfl_down_sync(FULL, m[j], d);
            if (ok) m[j] += v;
        }
    }
    if (head) red_row(g_S + (size_t)to * ROW, m);
}

__global__ void node_kernel(const int* __restrict__ ngi) {
    int i = blockIdx.x * blockDim.x + threadIdx.x;
    if (i >= NN) return;
    int g = ngi[i];
    const float* srow = g_S + (size_t)i * ROW;
    float s[10];
    ld_v8(srow, s);
    asm("ld.global.nc.v2.f32 {%0,%1}, [%2];" : "=f"(s[8]), "=f"(s[9]) : "l"(srow + 8));
    red_row(g_gs + (size_t)g * ROW, s);
}

__global__ void out_kernel(const float* __restrict__ Wo, const float* __restrict__ bo,
                           float* __restrict__ out) {
    int g = blockIdx.x * blockDim.x + threadIdx.x;
    if (g >= GG) return;
    float ev[4];
#pragma unroll
    for (int k = 0; k < 4; k++) ev[k] = bo[k];
#pragma unroll
    for (int j = 0; j < 10; j++) {
        float s = g_gs[g * ROW + j];
#pragma unroll
        for (int k = 0; k < 4; k++) ev[k] += s * Wo[j*4+k];
    }
    out[4*g+0] = ev[0];
    out[4*g+1] = softplus_acc(ev[1]);
    out[4*g+2] = softplus_acc(ev[2]) + 1.0f;
    out[4*g+3] = softplus_acc(ev[3]);
}

extern "C" void kernel_launch(void* const* d_in, const int* in_sizes, int n_in,
                              void* d_out, int out_size) {
    const float* coords = (const float*)d_in[0];
    const float* el     = (const float*)d_in[1];
    const float* evv    = (const float*)d_in[2];
    const float* Wm     = (const float*)d_in[3];
    const float* bm     = (const float*)d_in[4];
    const float* Wo     = (const float*)d_in[5];
    const float* bo     = (const float*)d_in[6];
    const int*   nf     = (const int*)d_in[7];
    const int*   nt     = (const int*)d_in[8];
    const int*   ngi    = (const int*)d_in[9];
    float* out = (float*)d_out;

    const int TB = 256;
    int grid_init = (NN * ROW + TB - 1) / TB;
    int grid_half = (EE / 2 + TB - 1) / TB;   // 12500 (paired kernels)
    int grid_node = (NN + TB - 1) / TB;
    int grid_out  = (GG + TB - 1) / TB;

    // build: hist -> scan -> to-sorted records
    init_kernel<<<grid_init, TB>>>(coords);
    hist_kernel<<<grid_half, TB>>>(nt);
    scan1_kernel<<<NB1, SBS>>>();
    scan2_kernel<<<1, SBS>>>();
    scan3_kernel<<<NB1, SBS>>>();
    scatter_kernel<<<grid_half, TB>>>(nf, nt, el, evv);

    // round 1: state0 = 0 -> S = state1
    round_kernel<true><<<grid_half, TB>>>(Wm, bm);
    pmat_kernel<<<grid_node, TB>>>(Wm, bm);             // M = fp16(P(state1))
    // round 2
    round_kernel<false><<<grid_half, TB>>>(Wm, bm);
    pmat_kernel<<<grid_node, TB>>>(Wm, bm);             // M = fp16(P(state2))
    // round 3
    round_kernel<false><<<grid_half, TB>>>(Wm, bm);
    // graph reduce + output head
    node_kernel<<<grid_node, TB>>>(ngi);
    out_kernel<<<grid_out, TB>>>(Wo, bo, out);
}

// round 17
// speedup vs baseline: 3.8747x; 1.0236x over previous
#include <cuda_runtime.h>
#include <cuda_bf16.h>
#include <cuda_fp16.h>
#include <math.h>

#define NN 200000
#define EE 6400000
#define GG 2000
#define ROW 16      // floats per fp32 state row (64B)
#define MROW 16     // halves per fp16 P-mirror row (32B)
#define SBS 512
#define NB1 ((NN + SBS - 1) / SBS)

__device__ __align__(256) float  g_S[NN * ROW];    // fp32 state accumulator
__device__ __align__(256) __half g_M[NN * MROW];   // fp16 mirror of P[n] = b + s·W + g1·W11
__device__ __align__(16)  float4 g_c4[NN];         // {coord.xyz, g1}
__device__ __align__(256) float  g_gs[GG * ROW];
// 32B record per edge, sorted by `to`: {el, g1, g3, cf.x, cf.y, cf.z, from, to}
__device__ __align__(32)  float4 g_rec[(size_t)EE * 2];
__device__ int g_off[NN];
__device__ int g_part[SBS];
__device__ int g_cnt[NN];

// HW tanh (MUFU.TANH, sm_75+): 1 op on the idle MUFU pipe instead of ~8 fma-pipe ops.
__device__ __forceinline__ float tanh_hw(float x) {
    float y;
    asm("tanh.approx.f32 %0, %1;" : "=f"(y) : "f"(x));
    return y;
}
__device__ __forceinline__ float softplus_acc(float x) {
    return log1pf(expf(-fabsf(x))) + fmaxf(x, 0.0f);
}
__device__ __forceinline__ void ld_v8(const float* p, float* s) {
    asm("ld.global.nc.v8.f32 {%0,%1,%2,%3,%4,%5,%6,%7}, [%8];"
        : "=f"(s[0]), "=f"(s[1]), "=f"(s[2]), "=f"(s[3]),
          "=f"(s[4]), "=f"(s[5]), "=f"(s[6]), "=f"(s[7])
        : "l"(p));
}
__device__ __forceinline__ void st_v8(float* p, const float* s) {
    asm volatile("st.global.v8.f32 [%0], {%1,%2,%3,%4,%5,%6,%7,%8};"
                 :: "l"(p), "f"(s[0]), "f"(s[1]), "f"(s[2]), "f"(s[3]),
                    "f"(s[4]), "f"(s[5]), "f"(s[6]), "f"(s[7]) : "memory");
}
__device__ __forceinline__ void red_v4(float* p, float a, float b, float c, float d) {
    asm volatile("red.global.add.v4.f32 [%0], {%1,%2,%3,%4};"
                 :: "l"(p), "f"(a), "f"(b), "f"(c), "f"(d) : "memory");
}
__device__ __forceinline__ void red_v2(float* p, float a, float b) {
    asm volatile("red.global.add.v2.f32 [%0], {%1,%2};"
                 :: "l"(p), "f"(a), "f"(b) : "memory");
}
__device__ __forceinline__ void red_row(float* dst, const float* a) {
    red_v4(dst,     a[0], a[1], a[2], a[3]);
    red_v4(dst + 4, a[4], a[5], a[6], a[7]);
    red_v2(dst + 8, a[8], a[9]);
}

__global__ void init_kernel(const float* __restrict__ coords) {
    int i = blockIdx.x * blockDim.x + threadIdx.x;
    if (i < NN * ROW) g_S[i] = 0.f;
    if (i < NN) {
        float x = coords[3*i], y = coords[3*i+1], z = coords[3*i+2];
        g_c4[i] = make_float4(x, y, z, fabsf(x) + fabsf(y) + fabsf(z));  // .w = g1
    }
    if (i < NN)       g_cnt[i] = 0;
    if (i < GG * ROW) g_gs[i] = 0.f;
}

// 2 edges per thread
__global__ void hist_kernel(const int* __restrict__ nt) {
    int t = blockIdx.x * blockDim.x + threadIdx.x;
    int e = 2 * t;
    if (e < EE) {
        atomicAdd(&g_cnt[nt[e]], 1);
        atomicAdd(&g_cnt[nt[e + 1]], 1);
    }
}

__global__ void scan1_kernel() {
    __shared__ int s[SBS];
    int tid = threadIdx.x;
    int gid = blockIdx.x * SBS + tid;
    int v = (gid < NN) ? g_cnt[gid] : 0;
    s[tid] = v;
    __syncthreads();
#pragma unroll
    for (int d = 1; d < SBS; d <<= 1) {
        int t = (tid >= d) ? s[tid - d] : 0;
        __syncthreads();
        s[tid] += t;
        __syncthreads();
    }
    if (gid < NN) g_off[gid] = s[tid] - v;
    if (tid == SBS - 1) g_part[blockIdx.x] = s[SBS - 1];
}

__global__ void scan2_kernel() {
    __shared__ int s[SBS];
    int tid = threadIdx.x;
    int v = (tid < NB1) ? g_part[tid] : 0;
    s[tid] = v;
    __syncthreads();
#pragma unroll
    for (int d = 1; d < SBS; d <<= 1) {
        int t = (tid >= d) ? s[tid - d] : 0;
        __syncthreads();
        s[tid] += t;
        __syncthreads();
    }
    if (tid < NB1) g_part[tid] = s[tid] - v;
}

__global__ void scan3_kernel() {
    int gid = blockIdx.x * SBS + threadIdx.x;
    if (gid < NN) g_off[gid] += g_part[blockIdx.x];
}

// 2 edges per thread; MLP-2 on gather/bump/store.
__global__ void scatter_kernel(const int* __restrict__ nf, const int* __restrict__ nt,
                               const float* __restrict__ el, const float* __restrict__ ev) {
    int t = blockIdx.x * blockDim.x + threadIdx.x;
    int e = 2 * t;
    if (e >= EE) return;

#pragma unroll
    for (int q = 0; q < 2; q++) {
        int ee = e + q;
        int from = nf[ee];
        int to   = nt[ee];
        float4 cf = g_c4[from];      // .w = g1(from)
        float e0 = ev[3*ee], e1 = ev[3*ee+1], e2 = ev[3*ee+2];

        float r[8];
        r[0] = el[ee];
        r[1] = cf.w;                                   // g1
        r[2] = cf.x*e0 + cf.y*e1 + cf.z*e2;            // g3
        r[3] = cf.x; r[4] = cf.y; r[5] = cf.z;
        r[6] = __int_as_float(from);
        r[7] = __int_as_float(to);

        int pos = atomicAdd(&g_off[to], 1);
        st_v8((float*)(g_rec + 2*(size_t)pos), r);
    }
}

// Per-node precompute: P[n] = b + s[n]·W_state + g1(n)*W11  -> fp16 mirror.
__global__ void pmat_kernel(const float* __restrict__ Wm, const float* __restrict__ bm) {
    __shared__ float sW[140];
    __shared__ float sB[10];
    int tid = threadIdx.x;
    if (tid < 140) sW[tid] = Wm[tid];
    if (tid < 10)  sB[tid] = bm[tid];
    __syncthreads();

    int n = blockIdx.x * blockDim.x + tid;
    if (n >= NN) return;

    const float* srow = g_S + (size_t)n * ROW;
    float s[10];
    ld_v8(srow, s);
    asm("ld.global.nc.v2.f32 {%0,%1}, [%2];" : "=f"(s[8]), "=f"(s[9]) : "l"(srow + 8));
    float g1 = g_c4[n].w;

    float P[10];
#pragma unroll
    for (int j = 0; j < 10; j++) P[j] = sB[j] + g1 * sW[110 + j];
#pragma unroll
    for (int i = 0; i < 10; i++) {
#pragma unroll
        for (int j = 0; j < 10; j++) P[j] += s[i] * sW[i*10 + j];
    }

    float w[8];
    unsigned u[8];
#pragma unroll
    for (int k = 0; k < 5; k++) {
        __half2 h = __floats2half2_rn(P[2*k], P[2*k+1]);
        u[k] = *reinterpret_cast<unsigned*>(&h);
    }
    u[5] = u[6] = u[7] = 0u;
#pragma unroll
    for (int k = 0; k < 8; k++) w[k] = __uint_as_float(u[k]);
    st_v8((float*)(g_M + (size_t)n * MROW), w);
}

// Compute one edge message from its record (weights in smem sG/sB).
template <bool FIRST>
__device__ __forceinline__ void edge_msg(const float* r, const float* sG, const float* sB,
                                         float* m) {
    // g2 = cf · c_to  (sorted `to` => near-broadcast c4 load)
    int to = __float_as_int(r[7]);
    float4 ct = g_c4[to];
    float g2 = r[3]*ct.x + r[4]*ct.y + r[5]*ct.z;

    if (FIRST) {
#pragma unroll
        for (int j = 0; j < 10; j++)
            m[j] = sB[j] + r[0]*sG[j] + r[1]*sG[10+j] + g2*sG[20+j] + r[2]*sG[30+j];
    } else {
        int from = __float_as_int(r[6]);
        float raw[8];
        ld_v8((const float*)(g_M + (size_t)from * MROW), raw);
#pragma unroll
        for (int k = 0; k < 5; k++) {
            unsigned u = __float_as_uint(raw[k]);
            __half2 h = *reinterpret_cast<__half2*>(&u);
            float2 f = __half22float2(h);
            m[2*k]   = f.x;
            m[2*k+1] = f.y;
        }
#pragma unroll
        for (int j = 0; j < 10; j++)
            m[j] += r[0]*sG[j] + g2*sG[20+j] + r[2]*sG[30+j];
    }
#pragma unroll
    for (int j = 0; j < 10; j++) m[j] = tanh_hw(m[j]);
}

// Paired round: each thread handles sorted edges 2t, 2t+1.
// ~97% of pairs share `to` -> local combine; else rare direct red of the first.
template <bool FIRST>
__global__ void __launch_bounds__(256) round_kernel(
        const float* __restrict__ Wm, const float* __restrict__ bm) {
    __shared__ float sG[40];   // rows 10..13 of W (el, g1, g2, g3)
    __shared__ float sB[10];
    int tid = threadIdx.x;
    if (tid < 40) sG[tid] = Wm[100 + tid];
    if (tid < 10) sB[tid] = bm[tid];
    __syncthreads();

    int t = blockIdx.x * blockDim.x + tid;   // t in [0, EE/2); EE/2 % 256 == 0
    int lane = tid & 31;
    size_t e = 2 * (size_t)t;

    float ra[8], rb[8];
    ld_v8((const float*)(g_rec + 2*e), ra);
    ld_v8((const float*)(g_rec + 2*e + 2), rb);
    int to_a = __float_as_int(ra[7]);
    int to_b = __float_as_int(rb[7]);

    float ma[10], mb[10];
    edge_msg<FIRST>(ra, sG, sB, ma);
    edge_msg<FIRST>(rb, sG, sB, mb);

    float m[10];
    if (to_a == to_b) {
#pragma unroll
        for (int j = 0; j < 10; j++) m[j] = ma[j] + mb[j];
    } else {
        red_row(g_S + (size_t)to_a * ROW, ma);   // rare (~3%)
#pragma unroll
        for (int j = 0; j < 10; j++) m[j] = mb[j];
    }
    int to = to_b;

    // Segmented suffix-scan over equal-`to` runs (to sorted across lanes).
    const unsigned FULL = 0xFFFFFFFFu;
    int tprev = __shfl_up_sync(FULL, to, 1);
    bool head = (lane == 0) || (tprev != to);
    unsigned hm = __ballot_sync(FULL, head);
    unsigned mask_after = hm & ~((2u << lane) - 1u);
    int seg_end = mask_after ? (__ffs(mask_after) - 2) : 31;
#pragma unroll
    for (int d = 1; d < 32; d <<= 1) {
        bool ok = (lane + d) <= seg_end;
#pragma unroll
        for (int j = 0; j < 10; j++) {
            float v = __shfl_down_sync(FULL, m[j], d);
            if (ok) m[j] += v;
        }
    }
    if (head) red_row(g_S + (size_t)to * ROW, m);
}

__global__ void node_kernel(const int* __restrict__ ngi) {
    int i = blockIdx.x * blockDim.x + threadIdx.x;
    if (i >= NN) return;
    int g = ngi[i];
    const float* srow = g_S + (size_t)i * ROW;
    float s[10];
    ld_v8(srow, s);
    asm("ld.global.nc.v2.f32 {%0,%1}, [%2];" : "=f"(s[8]), "=f"(s[9]) : "l"(srow + 8));
    red_row(g_gs + (size_t)g * ROW, s);
}

__global__ void out_kernel(const float* __restrict__ Wo, const float* __restrict__ bo,
                           float* __restrict__ out) {
    int g = blockIdx.x * blockDim.x + threadIdx.x;
    if (g >= GG) return;
    float ev[4];
#pragma unroll
    for (int k = 0; k < 4; k++) ev[k] = bo[k];
#pragma unroll
    for (int j = 0; j < 10; j++) {
        float s = g_gs[g * ROW + j];
#pragma unroll
        for (int k = 0; k < 4; k++) ev[k] += s * Wo[j*4+k];
    }
    out[4*g+0] = ev[0];
    out[4*g+1] = softplus_acc(ev[1]);
    out[4*g+2] = softplus_acc(ev[2]) + 1.0f;
    out[4*g+3] = softplus_acc(ev[3]);
}

extern "C" void kernel_launch(void* const* d_in, const int* in_sizes, int n_in,
                              void* d_out, int out_size) {
    const float* coords = (const float*)d_in[0];
    const float* el     = (const float*)d_in[1];
    const float* evv    = (const float*)d_in[2];
    const float* Wm     = (const float*)d_in[3];
    const float* bm     = (const float*)d_in[4];
    const float* Wo     = (const float*)d_in[5];
    const float* bo     = (const float*)d_in[6];
    const int*   nf     = (const int*)d_in[7];
    const int*   nt     = (const int*)d_in[8];
    const int*   ngi    = (const int*)d_in[9];
    float* out = (float*)d_out;

    const int TB = 256;
    int grid_init = (NN * ROW + TB - 1) / TB;
    int grid_half = (EE / 2 + TB - 1) / TB;   // 12500 (paired kernels)
    int grid_node = (NN + TB - 1) / TB;
    int grid_out  = (GG + TB - 1) / TB;

    // build: hist -> scan -> to-sorted records
    init_kernel<<<grid_init, TB>>>(coords);
    hist_kernel<<<grid_half, TB>>>(nt);
    scan1_kernel<<<NB1, SBS>>>();
    scan2_kernel<<<1, SBS>>>();
    scan3_kernel<<<NB1, SBS>>>();
    scatter_kernel<<<grid_half, TB>>>(nf, nt, el, evv);

    // round 1: state0 = 0 -> S = state1
    round_kernel<true><<<grid_half, TB>>>(Wm, bm);
    pmat_kernel<<<grid_node, TB>>>(Wm, bm);             // M = fp16(P(state1))
    // round 2
    round_kernel<false><<<grid_half, TB>>>(Wm, bm);
    pmat_kernel<<<grid_node, TB>>>(Wm, bm);             // M = fp16(P(state2))
    // round 3
    round_kernel<false><<<grid_half, TB>>>(Wm, bm);
    // graph reduce + output head
    node_kernel<<<grid_node, TB>>>(ngi);
    out_kernel<<<grid_out, TB>>>(Wo, bo, out);
}